// round 1
// baseline (speedup 1.0000x reference)
#include <cuda_runtime.h>
#include <cstdint>

#define B_ 16
#define N_ 1024
#define D_ 768

static const float SCALE_ = 0.03608439182435161f; // 768^-0.5

// Scratch (device globals: allocation-free contract)
__device__ float g_K[(size_t)B_ * N_ * D_];   // 48 MB: k = y @ W^T
__device__ float g_S[(size_t)B_ * N_ * N_];   // 64 MB: scores -> attn
__device__ float g_Q[(size_t)N_ * N_];        // 4 MB : pos softmax

typedef unsigned long long ull;

// ---------------- packed f32x2 helpers ----------------
__device__ __forceinline__ ull dup2(float x) {
    ull r; asm("mov.b64 %0, {%1, %1};" : "=l"(r) : "f"(x)); return r;
}
__device__ __forceinline__ void fma2(ull& c, ull a, ull b) {
    asm("fma.rn.f32x2 %0, %1, %2, %3;" : "=l"(c) : "l"(a), "l"(b), "l"(c));
}
__device__ __forceinline__ float lo32(ull v) { return __uint_as_float((unsigned)v); }
__device__ __forceinline__ float hi32(ull v) { return __uint_as_float((unsigned)(v >> 32)); }

// ---------------- SGEMM 64x64x16, 256 threads, 4x4 microtile ----------------
// BT=true : C = A(MxK,row) * B(NxK,row)^T   (NT)
// BT=false: C = A(MxK,row) * B(KxN,row)     (NN)
// All of M,N divisible by 64; K divisible by 16. Batched via blockIdx.z.
template <bool BT>
__global__ void __launch_bounds__(256) sgemm64(
    const float* __restrict__ A, const float* __restrict__ Bm, float* __restrict__ C,
    int M, int Nn, int K, int lda, int ldb, int ldc,
    size_t sA, size_t sB, size_t sC, float alpha)
{
    __shared__ __align__(16) float As[16][68];
    __shared__ __align__(16) float Bs[16][68];

    const int tid = threadIdx.x;
    const int tx = tid & 15;      // n direction (4 cols each)
    const int ty = tid >> 4;      // m direction (4 rows each)
    const int m0 = blockIdx.y * 64, n0 = blockIdx.x * 64;

    A  += (size_t)blockIdx.z * sA;
    Bm += (size_t)blockIdx.z * sB;
    C  += (size_t)blockIdx.z * sC;

    // A tile loader: 64 rows x 16 k, one float4 per thread
    const int ar = tid >> 2, aq = (tid & 3) * 4;
    const float* Aptr = A + (size_t)(m0 + ar) * lda + aq;

    // B tile loader
    int br, bq;
    const float* Bptr;
    if (BT) { br = tid >> 2;  bq = (tid & 3)  * 4; Bptr = Bm + (size_t)(n0 + br) * ldb + bq; }
    else    { br = tid >> 4;  bq = (tid & 15) * 4; Bptr = Bm + (size_t)br * ldb + n0 + bq; }

    ull acc[4][2];
#pragma unroll
    for (int i = 0; i < 4; i++) { acc[i][0] = 0ull; acc[i][1] = 0ull; }

    float4 aReg = *(const float4*)Aptr;
    float4 bReg = *(const float4*)Bptr;

    const int KT = K >> 4;
    for (int kt = 0; kt < KT; ++kt) {
        As[aq + 0][ar] = aReg.x; As[aq + 1][ar] = aReg.y;
        As[aq + 2][ar] = aReg.z; As[aq + 3][ar] = aReg.w;
        if (BT) {
            Bs[bq + 0][br] = bReg.x; Bs[bq + 1][br] = bReg.y;
            Bs[bq + 2][br] = bReg.z; Bs[bq + 3][br] = bReg.w;
        } else {
            *(float4*)&Bs[br][bq] = bReg;
        }
        __syncthreads();

        if (kt + 1 < KT) {  // prefetch next tile into registers
            aReg = *(const float4*)(Aptr + (size_t)(kt + 1) * 16);
            bReg = BT ? *(const float4*)(Bptr + (size_t)(kt + 1) * 16)
                      : *(const float4*)(Bptr + (size_t)(kt + 1) * 16 * ldb);
        }

#pragma unroll
        for (int k = 0; k < 16; k++) {
            float4 a4 = *(const float4*)&As[k][ty * 4];
            ull b0 = *(const ull*)&Bs[k][tx * 4];
            ull b1 = *(const ull*)(&Bs[k][tx * 4] + 2);
            ull a0 = dup2(a4.x), a1 = dup2(a4.y), a2 = dup2(a4.z), a3 = dup2(a4.w);
            fma2(acc[0][0], a0, b0); fma2(acc[0][1], a0, b1);
            fma2(acc[1][0], a1, b0); fma2(acc[1][1], a1, b1);
            fma2(acc[2][0], a2, b0); fma2(acc[2][1], a2, b1);
            fma2(acc[3][0], a3, b0); fma2(acc[3][1], a3, b1);
        }
        __syncthreads();
    }

#pragma unroll
    for (int i = 0; i < 4; i++) {
        float4 v;
        v.x = lo32(acc[i][0]) * alpha; v.y = hi32(acc[i][0]) * alpha;
        v.z = lo32(acc[i][1]) * alpha; v.w = hi32(acc[i][1]) * alpha;
        *(float4*)&C[(size_t)(m0 + ty * 4 + i) * ldc + n0 + tx * 4] = v;
    }
}

// ---------------- block reductions (256 threads) ----------------
__device__ __forceinline__ float warpMax(float v) {
#pragma unroll
    for (int o = 16; o; o >>= 1) v = fmaxf(v, __shfl_xor_sync(0xffffffffu, v, o));
    return v;
}
__device__ __forceinline__ float warpSum(float v) {
#pragma unroll
    for (int o = 16; o; o >>= 1) v += __shfl_xor_sync(0xffffffffu, v, o);
    return v;
}
__device__ float blockMax256(float v) {
    __shared__ float red[8];
    v = warpMax(v);
    if ((threadIdx.x & 31) == 0) red[threadIdx.x >> 5] = v;
    __syncthreads();
    float r = red[0];
#pragma unroll
    for (int i = 1; i < 8; i++) r = fmaxf(r, red[i]);
    __syncthreads();
    return r;
}
__device__ float blockSum256(float v) {
    __shared__ float red2[8];
    v = warpSum(v);
    if ((threadIdx.x & 31) == 0) red2[threadIdx.x >> 5] = v;
    __syncthreads();
    float r = red2[0];
#pragma unroll
    for (int i = 1; i < 8; i++) r += red2[i];
    __syncthreads();
    return r;
}

// ---------------- positional softmax: Q[p][n] = softmax_n(coords[p,n,:] . pe[p,:]) ----
__global__ void __launch_bounds__(256) pos_kernel(
    const float* __restrict__ coords, const float* __restrict__ pe, float* __restrict__ Q)
{
    const int p = blockIdx.x;
    __shared__ float pesh[6];
    if (threadIdx.x < 6) pesh[threadIdx.x] = pe[p * 6 + threadIdx.x];
    __syncthreads();

    const float* cbase = coords + (size_t)p * N_ * 6;
    float z[4];
#pragma unroll
    for (int i = 0; i < 4; i++) {
        const int n = i * 256 + threadIdx.x;
        const float* c = cbase + (size_t)n * 6;
        z[i] = c[0] * pesh[0] + c[1] * pesh[1] + c[2] * pesh[2]
             + c[3] * pesh[3] + c[4] * pesh[4] + c[5] * pesh[5];
    }
    float m = fmaxf(fmaxf(z[0], z[1]), fmaxf(z[2], z[3]));
    m = blockMax256(m);
    float e[4], s = 0.f;
#pragma unroll
    for (int i = 0; i < 4; i++) { e[i] = expf(z[i] - m); s += e[i]; }
    s = blockSum256(s);
    const float inv = 1.f / s;
#pragma unroll
    for (int i = 0; i < 4; i++)
        Q[(size_t)p * N_ + i * 256 + threadIdx.x] = e[i] * inv;
}

// ---------------- row softmax + gate mix + entropy/hmap; attn written back into S ----
__global__ void __launch_bounds__(256) mix_kernel(
    float* __restrict__ S, const float* __restrict__ Q,
    const float* __restrict__ gating, const float* __restrict__ temp,
    float* __restrict__ hmap)
{
    const int row = blockIdx.x;        // b*N + n
    const int n = row & (N_ - 1);
    float* s = S + (size_t)row * N_;
    const float* q = Q + (size_t)n * N_;
    const int base = threadIdx.x * 4;

    float4 v = *(const float4*)(s + base);
    float m = fmaxf(fmaxf(v.x, v.y), fmaxf(v.z, v.w));
    m = blockMax256(m);

    float4 e;
    e.x = expf(v.x - m); e.y = expf(v.y - m);
    e.z = expf(v.z - m); e.w = expf(v.w - m);
    float ssum = e.x + e.y + e.z + e.w;
    ssum = blockSum256(ssum);
    const float inv = 1.f / ssum;

    const float g  = 1.f / (1.f + expf(-gating[0]));
    const float og = 1.f - g;
    float4 qv = *(const float4*)(q + base);

    float4 a;
    a.x = og * e.x * inv + g * qv.x;
    a.y = og * e.y * inv + g * qv.y;
    a.z = og * e.z * inv + g * qv.z;
    a.w = og * e.w * inv + g * qv.w;

    float H = -(a.x * logf(a.x + 1e-8f) + a.y * logf(a.y + 1e-8f)
              + a.z * logf(a.z + 1e-8f) + a.w * logf(a.w + 1e-8f));
    H = blockSum256(H);

    *(float4*)(s + base) = a;
    if (threadIdx.x == 0) {
        const float t = temp[0];
        const float sig = 1.f / (1.f + expf(-t * H));
        hmap[row] = 2.f * (1.f - sig);
    }
}

// ---------------- launch ----------------
extern "C" void kernel_launch(void* const* d_in, const int* in_sizes, int n_in,
                              void* d_out, int out_size)
{
    const float* x      = (const float*)d_in[0];
    const float* y      = (const float*)d_in[1];
    const float* coords = (const float*)d_in[2];
    const float* W      = (const float*)d_in[3];
    const float* pe     = (const float*)d_in[4];
    const float* gating = (const float*)d_in[5];
    const float* temp   = (const float*)d_in[6];

    float* out  = (float*)d_out;                       // [B,N,D]
    float* hmap = out + (size_t)B_ * N_ * D_;          // [B,N,1]

    float *Kb, *Sb, *Qb;
    cudaGetSymbolAddress((void**)&Kb, g_K);
    cudaGetSymbolAddress((void**)&Sb, g_S);
    cudaGetSymbolAddress((void**)&Qb, g_Q);

    // 1) Kb = y @ W^T   (M=16384, N=768, K=768, NT)
    sgemm64<true><<<dim3(D_ / 64, (B_ * N_) / 64, 1), 256>>>(
        y, W, Kb, B_ * N_, D_, D_, D_, D_, D_, 0, 0, 0, 1.0f);

    // 2) positional softmax Q
    pos_kernel<<<N_, 256>>>(coords, pe, Qb);

    // 3) S = (x @ Kb^T) * SCALE, batched over B (NT)
    sgemm64<true><<<dim3(N_ / 64, N_ / 64, B_), 256>>>(
        x, Kb, Sb, N_, N_, D_, D_, D_, N_,
        (size_t)N_ * D_, (size_t)N_ * D_, (size_t)N_ * N_, SCALE_);

    // 4) softmax rows of S, mix with Q, entropy -> hmap; attn written into S
    mix_kernel<<<B_ * N_, 256>>>(Sb, Qb, gating, temp, hmap);

    // 5) out = attn @ y, batched over B (NN)
    sgemm64<false><<<dim3(D_ / 64, N_ / 64, B_), 256>>>(
        Sb, y, out, N_, D_, N_, N_, D_, D_,
        (size_t)N_ * N_, (size_t)N_ * D_, (size_t)N_ * D_, 1.0f);
}

// round 3
// speedup vs baseline: 2.3230x; 2.3230x over previous
#include <cuda_runtime.h>
#include <cuda_bf16.h>
#include <cstdint>

#define B_ 16
#define N_ 1024
#define D_ 768

typedef __nv_bfloat16 bf16;

static const float SCALE_ = 0.03608439182435161f; // 768^-0.5

// ---------------- scratch (device globals: allocation-free contract) ----------------
__device__ __align__(16) float g_S[(size_t)B_ * N_ * N_];   // 64 MB fp32 scores
__device__ __align__(16) float g_Q[(size_t)N_ * N_];        // 4 MB  pos softmax
__device__ __align__(16) bf16 g_xh[(size_t)B_ * N_ * D_], g_xl[(size_t)B_ * N_ * D_];
__device__ __align__(16) bf16 g_yh[(size_t)B_ * N_ * D_], g_yl[(size_t)B_ * N_ * D_];
__device__ __align__(16) bf16 g_wh[(size_t)D_ * D_],      g_wl[(size_t)D_ * D_];
__device__ __align__(16) bf16 g_kh[(size_t)B_ * N_ * D_], g_kl[(size_t)B_ * N_ * D_];
__device__ __align__(16) bf16 g_yth[(size_t)B_ * D_ * N_], g_ytl[(size_t)B_ * D_ * N_];
__device__ __align__(16) bf16 g_ah[(size_t)B_ * N_ * N_],  g_al[(size_t)B_ * N_ * N_];

// ---------------- helpers ----------------
__device__ __forceinline__ uint32_t smem_u32(const void* p) {
    uint32_t a;
    asm("{ .reg .u64 t; cvta.to.shared.u64 t, %1; cvt.u32.u64 %0, t; }" : "=r"(a) : "l"(p));
    return a;
}
#define CP_COMMIT() asm volatile("cp.async.commit_group;" ::: "memory")
#define CP_WAIT1()  asm volatile("cp.async.wait_group 1;" ::: "memory")

__device__ __forceinline__ void mma16816(float* c, const uint32_t* a, const uint32_t* b) {
    asm volatile(
        "mma.sync.aligned.m16n8k16.row.col.f32.bf16.bf16.f32 "
        "{%0,%1,%2,%3}, {%4,%5,%6,%7}, {%8,%9}, {%0,%1,%2,%3};"
        : "+f"(c[0]), "+f"(c[1]), "+f"(c[2]), "+f"(c[3])
        : "r"(a[0]), "r"(a[1]), "r"(a[2]), "r"(a[3]), "r"(b[0]), "r"(b[1]));
}

// ---------------- HMMA split-bf16 GEMM: C[M,N] = alpha * sum(A*B^T terms) ----------
// A[M,K], B[N,K] row-major, each as (hi, lo) bf16 pair. 3-term accumulation:
// Ah*Bh + Ah*Bl + Al*Bh. Block 128x128, K-chunk 32, 8 warps (warp tile 64x32).
// SMEM tile: 128 rows x 32 cols bf16, padded row stride 80 bytes (conflict-free).
#define TILE_P 10240         // 128 * 80
#define STAGE_P 40960        // 4 tiles
#define SMEM_BYTES (2 * STAGE_P)

__device__ __forceinline__ void fill_tile(uint32_t dst, const bf16* __restrict__ g,
                                          int ld, int r0, int k0, int tid) {
#pragma unroll
    for (int it = 0; it < 2; it++) {
        int idx = it * 256 + tid;
        int r = idx >> 2, seg = idx & 3;
        const bf16* src = g + (size_t)(r0 + r) * ld + k0 + seg * 8;
        asm volatile("cp.async.cg.shared.global [%0], [%1], 16;"
                     :: "r"(dst + r * 80 + seg * 16), "l"(src));
    }
}

template <bool SPLIT_OUT>
__global__ void __launch_bounds__(256, 1) gemm_mma(
    const bf16* __restrict__ Ah_, const bf16* __restrict__ Al_,
    const bf16* __restrict__ Bh_, const bf16* __restrict__ Bl_,
    float* __restrict__ C, bf16* __restrict__ Ch, bf16* __restrict__ Cl,
    int K, int lda, int ldb, int ldc,
    size_t sA, size_t sB, size_t sC, float alpha)
{
    extern __shared__ char sm[];
    const uint32_t sb = smem_u32(sm);
    const int tid = threadIdx.x, lane = tid & 31, w = tid >> 5;
    const int wm = w & 1, wn = w >> 1;          // warp grid 2(M) x 4(N)
    const int g = lane >> 2, tig = lane & 3;
    const int m0 = blockIdx.y * 128, n0 = blockIdx.x * 128;

    Ah_ += (size_t)blockIdx.z * sA; Al_ += (size_t)blockIdx.z * sA;
    Bh_ += (size_t)blockIdx.z * sB; Bl_ += (size_t)blockIdx.z * sB;

    const uint32_t aBase = (uint32_t)((wm * 64 + g) * 80 + tig * 4);
    const uint32_t bBase = (uint32_t)((wn * 32 + g) * 80 + tig * 4);

    float acc[4][4][4];
#pragma unroll
    for (int i = 0; i < 4; i++)
#pragma unroll
        for (int j = 0; j < 4; j++)
#pragma unroll
            for (int c = 0; c < 4; c++) acc[i][j][c] = 0.f;

    const int KT = K >> 5;

    // prologue: stage 0 = chunk 0, stage 1 = chunk 1
#pragma unroll
    for (int p = 0; p < 2; p++) {
        uint32_t S0 = sb + p * STAGE_P;
        fill_tile(S0 + 0 * TILE_P, Ah_, lda, m0, p * 32, tid);
        fill_tile(S0 + 1 * TILE_P, Al_, lda, m0, p * 32, tid);
        fill_tile(S0 + 2 * TILE_P, Bh_, ldb, n0, p * 32, tid);
        fill_tile(S0 + 3 * TILE_P, Bl_, ldb, n0, p * 32, tid);
        CP_COMMIT();
    }

    for (int kt = 0; kt < KT; ++kt) {
        CP_WAIT1();
        __syncthreads();
        const uint32_t soff = (kt & 1) * STAGE_P;
        const char* pAh = sm + soff + 0 * TILE_P;
        const char* pAl = sm + soff + 1 * TILE_P;
        const char* pBh = sm + soff + 2 * TILE_P;
        const char* pBl = sm + soff + 3 * TILE_P;

#pragma unroll
        for (int s = 0; s < 2; s++) {
            uint32_t ah[4][4], al[4][4], bh[4][2], bl[4][2];
#pragma unroll
            for (int mf = 0; mf < 4; mf++) {
                uint32_t o = aBase + mf * 1280 + s * 32;
                ah[mf][0] = *(const uint32_t*)(pAh + o);
                ah[mf][1] = *(const uint32_t*)(pAh + o + 640);
                ah[mf][2] = *(const uint32_t*)(pAh + o + 16);
                ah[mf][3] = *(const uint32_t*)(pAh + o + 656);
                al[mf][0] = *(const uint32_t*)(pAl + o);
                al[mf][1] = *(const uint32_t*)(pAl + o + 640);
                al[mf][2] = *(const uint32_t*)(pAl + o + 16);
                al[mf][3] = *(const uint32_t*)(pAl + o + 656);
            }
#pragma unroll
            for (int nf = 0; nf < 4; nf++) {
                uint32_t o = bBase + nf * 640 + s * 32;
                bh[nf][0] = *(const uint32_t*)(pBh + o);
                bh[nf][1] = *(const uint32_t*)(pBh + o + 16);
                bl[nf][0] = *(const uint32_t*)(pBl + o);
                bl[nf][1] = *(const uint32_t*)(pBl + o + 16);
            }
#pragma unroll
            for (int mf = 0; mf < 4; mf++)
#pragma unroll
                for (int nf = 0; nf < 4; nf++) {
                    mma16816(acc[mf][nf], ah[mf], bh[nf]);
                    mma16816(acc[mf][nf], ah[mf], bl[nf]);
                    mma16816(acc[mf][nf], al[mf], bh[nf]);
                }
        }
        __syncthreads();
        if (kt + 2 < KT) {
            const int k0 = (kt + 2) * 32;
            const uint32_t S0 = sb + soff;
            fill_tile(S0 + 0 * TILE_P, Ah_, lda, m0, k0, tid);
            fill_tile(S0 + 1 * TILE_P, Al_, lda, m0, k0, tid);
            fill_tile(S0 + 2 * TILE_P, Bh_, ldb, n0, k0, tid);
            fill_tile(S0 + 3 * TILE_P, Bl_, ldb, n0, k0, tid);
        }
        CP_COMMIT();   // empty group on tail iterations keeps wait_group(1) correct
    }

    // epilogue
#pragma unroll
    for (int mf = 0; mf < 4; mf++) {
#pragma unroll
        for (int nf = 0; nf < 4; nf++) {
            const int row = m0 + wm * 64 + mf * 16 + g;
            const int col = n0 + wn * 32 + nf * 8 + tig * 2;
            float c0 = acc[mf][nf][0] * alpha, c1 = acc[mf][nf][1] * alpha;
            float c2 = acc[mf][nf][2] * alpha, c3 = acc[mf][nf][3] * alpha;
            if (SPLIT_OUT) {
                bf16 h0 = __float2bfloat16_rn(c0), h1 = __float2bfloat16_rn(c1);
                bf16 h2 = __float2bfloat16_rn(c2), h3 = __float2bfloat16_rn(c3);
                bf16 l0 = __float2bfloat16_rn(c0 - __bfloat162float(h0));
                bf16 l1 = __float2bfloat16_rn(c1 - __bfloat162float(h1));
                bf16 l2 = __float2bfloat16_rn(c2 - __bfloat162float(h2));
                bf16 l3 = __float2bfloat16_rn(c3 - __bfloat162float(h3));
                bf16 ph0[2] = {h0, h1}, ph2[2] = {h2, h3};
                bf16 pl0[2] = {l0, l1}, pl2[2] = {l2, l3};
                *(uint32_t*)&Ch[(size_t)row * ldc + col]       = *(uint32_t*)ph0;
                *(uint32_t*)&Ch[(size_t)(row + 8) * ldc + col] = *(uint32_t*)ph2;
                *(uint32_t*)&Cl[(size_t)row * ldc + col]       = *(uint32_t*)pl0;
                *(uint32_t*)&Cl[(size_t)(row + 8) * ldc + col] = *(uint32_t*)pl2;
            } else {
                float* Cp = C + (size_t)blockIdx.z * sC;
                float2 v0 = {c0, c1}, v2 = {c2, c3};
                *(float2*)&Cp[(size_t)row * ldc + col]       = v0;
                *(float2*)&Cp[(size_t)(row + 8) * ldc + col] = v2;
            }
        }
    }
}

// ---------------- fp32 -> (hi,lo) bf16 split ----------------
__global__ void __launch_bounds__(256) split_k(const float4* __restrict__ in,
                                               uint2* __restrict__ hi, uint2* __restrict__ lo,
                                               int n4) {
    int i = blockIdx.x * 256 + threadIdx.x;
    if (i >= n4) return;
    float4 v = in[i];
    float xs[4] = {v.x, v.y, v.z, v.w};
    bf16 h[4], l[4];
#pragma unroll
    for (int j = 0; j < 4; j++) {
        h[j] = __float2bfloat16_rn(xs[j]);
        l[j] = __float2bfloat16_rn(xs[j] - __bfloat162float(h[j]));
    }
    hi[i] = *(uint2*)h;
    lo[i] = *(uint2*)l;
}

// ---------------- y [B,N,D] -> yT hi/lo [B,D,N] ----------------
__global__ void __launch_bounds__(256) split_T(const float* __restrict__ y,
                                               bf16* __restrict__ th, bf16* __restrict__ tl) {
    __shared__ float t[32][33];
    const int b = blockIdx.z;
    const float* Y = y + (size_t)b * N_ * D_;
    const int n0 = blockIdx.x * 32, d0 = blockIdx.y * 32;
    const int tx = threadIdx.x, ty = threadIdx.y;  // (32, 8)
#pragma unroll
    for (int i = 0; i < 4; i++)
        t[ty + i * 8][tx] = Y[(size_t)(n0 + ty + i * 8) * D_ + d0 + tx];
    __syncthreads();
    bf16* TH = th + (size_t)b * D_ * N_;
    bf16* TL = tl + (size_t)b * D_ * N_;
#pragma unroll
    for (int i = 0; i < 4; i++) {
        int r = ty + i * 8;
        float v = t[tx][r];
        bf16 h = __float2bfloat16_rn(v);
        TH[(size_t)(d0 + r) * N_ + n0 + tx] = h;
        TL[(size_t)(d0 + r) * N_ + n0 + tx] = __float2bfloat16_rn(v - __bfloat162float(h));
    }
}

// ---------------- block reductions (256 threads) ----------------
__device__ __forceinline__ float warpMax(float v) {
#pragma unroll
    for (int o = 16; o; o >>= 1) v = fmaxf(v, __shfl_xor_sync(0xffffffffu, v, o));
    return v;
}
__device__ __forceinline__ float warpSum(float v) {
#pragma unroll
    for (int o = 16; o; o >>= 1) v += __shfl_xor_sync(0xffffffffu, v, o);
    return v;
}
__device__ float blockMax256(float v) {
    __shared__ float red[8];
    v = warpMax(v);
    if ((threadIdx.x & 31) == 0) red[threadIdx.x >> 5] = v;
    __syncthreads();
    float r = red[0];
#pragma unroll
    for (int i = 1; i < 8; i++) r = fmaxf(r, red[i]);
    __syncthreads();
    return r;
}
__device__ float blockSum256(float v) {
    __shared__ float red2[8];
    v = warpSum(v);
    if ((threadIdx.x & 31) == 0) red2[threadIdx.x >> 5] = v;
    __syncthreads();
    float r = red2[0];
#pragma unroll
    for (int i = 1; i < 8; i++) r += red2[i];
    __syncthreads();
    return r;
}

// ---------------- positional softmax ----------------
__global__ void __launch_bounds__(256) pos_kernel(
    const float* __restrict__ coords, const float* __restrict__ pe, float* __restrict__ Q)
{
    const int p = blockIdx.x;
    __shared__ float pesh[6];
    if (threadIdx.x < 6) pesh[threadIdx.x] = pe[p * 6 + threadIdx.x];
    __syncthreads();

    const float* cbase = coords + (size_t)p * N_ * 6;
    float z[4];
#pragma unroll
    for (int i = 0; i < 4; i++) {
        const int n = i * 256 + threadIdx.x;
        const float* c = cbase + (size_t)n * 6;
        z[i] = c[0] * pesh[0] + c[1] * pesh[1] + c[2] * pesh[2]
             + c[3] * pesh[3] + c[4] * pesh[4] + c[5] * pesh[5];
    }
    float m = fmaxf(fmaxf(z[0], z[1]), fmaxf(z[2], z[3]));
    m = blockMax256(m);
    float e[4], s = 0.f;
#pragma unroll
    for (int i = 0; i < 4; i++) { e[i] = expf(z[i] - m); s += e[i]; }
    s = blockSum256(s);
    const float inv = 1.f / s;
#pragma unroll
    for (int i = 0; i < 4; i++)
        Q[(size_t)p * N_ + i * 256 + threadIdx.x] = e[i] * inv;
}

// -------- row softmax + gate mix + entropy; attn emitted as bf16 hi/lo --------
__global__ void __launch_bounds__(256) mix_kernel(
    const float* __restrict__ S, const float* __restrict__ Q,
    const float* __restrict__ gating, const float* __restrict__ temp,
    bf16* __restrict__ AH, bf16* __restrict__ AL, float* __restrict__ hmap)
{
    const int row = blockIdx.x;        // b*N + n
    const int n = row & (N_ - 1);
    const float* s = S + (size_t)row * N_;
    const float* q = Q + (size_t)n * N_;
    const int base = threadIdx.x * 4;

    float4 v = *(const float4*)(s + base);
    float m = fmaxf(fmaxf(v.x, v.y), fmaxf(v.z, v.w));
    m = blockMax256(m);

    float4 e;
    e.x = expf(v.x - m); e.y = expf(v.y - m);
    e.z = expf(v.z - m); e.w = expf(v.w - m);
    float ssum = e.x + e.y + e.z + e.w;
    ssum = blockSum256(ssum);
    const float inv = 1.f / ssum;

    const float g  = 1.f / (1.f + expf(-gating[0]));
    const float og = 1.f - g;
    float4 qv = *(const float4*)(q + base);

    float a[4];
    a[0] = og * e.x * inv + g * qv.x;
    a[1] = og * e.y * inv + g * qv.y;
    a[2] = og * e.z * inv + g * qv.z;
    a[3] = og * e.w * inv + g * qv.w;

    float H = -(a[0] * logf(a[0] + 1e-8f) + a[1] * logf(a[1] + 1e-8f)
              + a[2] * logf(a[2] + 1e-8f) + a[3] * logf(a[3] + 1e-8f));
    H = blockSum256(H);

    bf16 h[4], l[4];
#pragma unroll
    for (int j = 0; j < 4; j++) {
        h[j] = __float2bfloat16_rn(a[j]);
        l[j] = __float2bfloat16_rn(a[j] - __bfloat162float(h[j]));
    }
    *(uint2*)&AH[(size_t)row * N_ + base] = *(uint2*)h;
    *(uint2*)&AL[(size_t)row * N_ + base] = *(uint2*)l;

    if (threadIdx.x == 0) {
        const float t = temp[0];
        const float sig = 1.f / (1.f + expf(-t * H));
        hmap[row] = 2.f * (1.f - sig);
    }
}

// ---------------- launch ----------------
extern "C" void kernel_launch(void* const* d_in, const int* in_sizes, int n_in,
                              void* d_out, int out_size)
{
    const float* x      = (const float*)d_in[0];
    const float* y      = (const float*)d_in[1];
    const float* coords = (const float*)d_in[2];
    const float* W      = (const float*)d_in[3];
    const float* pe     = (const float*)d_in[4];
    const float* gating = (const float*)d_in[5];
    const float* temp   = (const float*)d_in[6];

    float* out  = (float*)d_out;                // [B,N,D]
    float* hmap = out + (size_t)B_ * N_ * D_;   // [B,N,1]

    float *Sb, *Qb;
    bf16 *xh, *xl, *yh, *yl, *wh, *wl, *kh, *kl, *yth, *ytl, *ah, *al;
    cudaGetSymbolAddress((void**)&Sb, g_S);
    cudaGetSymbolAddress((void**)&Qb, g_Q);
    cudaGetSymbolAddress((void**)&xh, g_xh);  cudaGetSymbolAddress((void**)&xl, g_xl);
    cudaGetSymbolAddress((void**)&yh, g_yh);  cudaGetSymbolAddress((void**)&yl, g_yl);
    cudaGetSymbolAddress((void**)&wh, g_wh);  cudaGetSymbolAddress((void**)&wl, g_wl);
    cudaGetSymbolAddress((void**)&kh, g_kh);  cudaGetSymbolAddress((void**)&kl, g_kl);
    cudaGetSymbolAddress((void**)&yth, g_yth); cudaGetSymbolAddress((void**)&ytl, g_ytl);
    cudaGetSymbolAddress((void**)&ah, g_ah);  cudaGetSymbolAddress((void**)&al, g_al);

    cudaFuncSetAttribute(gemm_mma<true>,  cudaFuncAttributeMaxDynamicSharedMemorySize, SMEM_BYTES);
    cudaFuncSetAttribute(gemm_mma<false>, cudaFuncAttributeMaxDynamicSharedMemorySize, SMEM_BYTES);

    const int nBND4 = (B_ * N_ * D_) / 4;
    const int nDD4  = (D_ * D_) / 4;

    split_k<<<(nBND4 + 255) / 256, 256>>>((const float4*)y, (uint2*)yh, (uint2*)yl, nBND4);
    split_k<<<(nBND4 + 255) / 256, 256>>>((const float4*)x, (uint2*)xh, (uint2*)xl, nBND4);
    split_k<<<(nDD4  + 255) / 256, 256>>>((const float4*)W, (uint2*)wh, (uint2*)wl, nDD4);
    split_T<<<dim3(N_ / 32, D_ / 32, B_), dim3(32, 8)>>>(y, yth, ytl);

    pos_kernel<<<N_, 256>>>(coords, pe, Qb);

    // 1) k = y @ W^T  (M=16384, N=768, K=768) -> kh/kl bf16 directly
    gemm_mma<true><<<dim3(D_ / 128, (B_ * N_) / 128, 1), 256, SMEM_BYTES>>>(
        yh, yl, wh, wl, nullptr, kh, kl, D_, D_, D_, D_, 0, 0, 0, 1.0f);

    // 2) S = (x @ k^T) * SCALE, batched over B -> fp32
    gemm_mma<false><<<dim3(N_ / 128, N_ / 128, B_), 256, SMEM_BYTES>>>(
        xh, xl, kh, kl, Sb, nullptr, nullptr, D_, D_, D_, N_,
        (size_t)N_ * D_, (size_t)N_ * D_, (size_t)N_ * N_, SCALE_);

    // 3) softmax + mix + entropy -> attn bf16 hi/lo + hmap
    mix_kernel<<<B_ * N_, 256>>>(Sb, Qb, gating, temp, ah, al, hmap);

    // 4) out = attn @ y (B operand = y^T per batch, K=1024)
    gemm_mma<false><<<dim3(D_ / 128, N_ / 128, B_), 256, SMEM_BYTES>>>(
        ah, al, yth, ytl, out, nullptr, nullptr, N_, N_, N_, D_,
        (size_t)N_ * N_, (size_t)D_ * N_, (size_t)N_ * D_, 1.0f);
}